// round 9
// baseline (speedup 1.0000x reference)
#include <cuda_runtime.h>
#include <cuda_fp16.h>
#include <math.h>
#include <cstdint>

#define S_LEN 2048
#define D_MODEL 1024
#define N_HEADS 16
#define D_KV 64
#define KE 2048              // A'/B' width: [hi(1024) | lo(1024)]
#define HSZ (S_LEN * 128)    // per-head Q'/K' plane (d'=128: [hi|lo])
#define HSZV (S_LEN * 64)    // per-head V plane

// ---------------- scratch (__device__ globals; no allocs) -------------------
__device__ float g_bias[N_HEADS * 4096];                 // [h][delta+2047]
__device__ __align__(16) __half g_A2[S_LEN * KE];        // A' rows: [Ah | Al]
__device__ __align__(16) __half g_B2[4096 * KE];         // B' rows: [Bh | Bl], W x256
__device__ __align__(16) __half g_Q2[N_HEADS * HSZ];     // [h][s][ Qh(64) | Ql(64) ]
__device__ __align__(16) __half g_K2[N_HEADS * HSZ];     // [h][s][ Kh(64) | Kl(64) ]
__device__ __align__(16) __half g_V [N_HEADS * HSZV];    // [h][s][64] single fp16

__device__ __forceinline__ uint32_t smem_u32(const void* p) {
    uint32_t a;
    asm("{ .reg .u64 t; cvta.to.shared.u64 t, %1; cvt.u32.u64 %0, t; }" : "=r"(a) : "l"(p));
    return a;
}

// ---------------- mma / ldmatrix / cp.async primitives ----------------------
__device__ __forceinline__ void ldm_x4(uint32_t* r, uint32_t addr) {
    asm volatile("ldmatrix.sync.aligned.m8n8.x4.shared.b16 {%0,%1,%2,%3}, [%4];"
                 : "=r"(r[0]), "=r"(r[1]), "=r"(r[2]), "=r"(r[3]) : "r"(addr));
}
__device__ __forceinline__ void ldm_x4t(uint32_t* r, uint32_t addr) {
    asm volatile("ldmatrix.sync.aligned.m8n8.x4.trans.shared.b16 {%0,%1,%2,%3}, [%4];"
                 : "=r"(r[0]), "=r"(r[1]), "=r"(r[2]), "=r"(r[3]) : "r"(addr));
}
__device__ __forceinline__ void mma_hf(float* d, const uint32_t* a, const uint32_t* b) {
    asm volatile("mma.sync.aligned.m16n8k16.row.col.f32.f16.f16.f32 "
                 "{%0,%1,%2,%3}, {%4,%5,%6,%7}, {%8,%9}, {%0,%1,%2,%3};"
                 : "+f"(d[0]), "+f"(d[1]), "+f"(d[2]), "+f"(d[3])
                 : "r"(a[0]), "r"(a[1]), "r"(a[2]), "r"(a[3]), "r"(b[0]), "r"(b[1]));
}
__device__ __forceinline__ void cp16(uint32_t saddr, const void* gaddr) {
    asm volatile("cp.async.cg.shared.global [%0], [%1], 16;" :: "r"(saddr), "l"(gaddr));
}
#define CP_COMMIT() asm volatile("cp.async.commit_group;" ::: "memory")
#define CP_WAIT(n)  asm volatile("cp.async.wait_group %0;" :: "n"(n) : "memory")

__device__ __forceinline__ uint32_t pack_f16(float lo, float hi) {
    uint32_t r;
    asm("cvt.rn.f16x2.f32 %0, %1, %2;" : "=r"(r) : "f"(hi), "f"(lo));
    return r;
}

// ---------------------------------------------------------------------------
// Bias LUT
// ---------------------------------------------------------------------------
__global__ void bias_kernel(const float* __restrict__ rel_bias) {
    int idx = blockIdx.x * blockDim.x + threadIdx.x;
    if (idx >= N_HEADS * 4095) return;
    int h = idx / 4095;
    int di = idx % 4095;
    int delta = di - 2047;
    int bucket = (delta > 0) ? 16 : 0;
    int rp = abs(delta);
    if (rp < 8) {
        bucket += rp;
    } else {
        float lr = logf((float)rp * 0.125f) / 2.7725887f;
        int large = 8 + (int)(lr * 8.0f);
        bucket += (large < 15) ? large : 15;
    }
    g_bias[h * 4096 + di] = rel_bias[bucket * N_HEADS + h];
}

// ---------------------------------------------------------------------------
// Converters: fp32 -> fp16 hi/lo split
// ---------------------------------------------------------------------------
__global__ void convA_kernel(const float* __restrict__ X) {
    int i = (blockIdx.x * blockDim.x + threadIdx.x) * 4;   // over 2048x1024
    int row = i >> 10, col = i & 1023;
    float4 v = *(const float4*)(X + i);
    float x[4] = {v.x, v.y, v.z, v.w};
    __half hi[4], lo[4];
#pragma unroll
    for (int u = 0; u < 4; u++) {
        hi[u] = __float2half_rn(x[u]);
        lo[u] = __float2half_rn(x[u] - __half2float(hi[u]));
    }
    __half* dst = g_A2 + (size_t)row * KE + col;
    *(__half2*)(dst + 0) = __halves2half2(hi[0], hi[1]);
    *(__half2*)(dst + 2) = __halves2half2(hi[2], hi[3]);
    *(__half2*)(dst + 1024) = __halves2half2(lo[0], lo[1]);
    *(__half2*)(dst + 1026) = __halves2half2(lo[2], lo[3]);
}

// Transpose + split W*256 into g_B2 rows [Bh|Bl]; z: 0=Wq 1=Wk 2=Wv 3=Wo
__global__ void convB_kernel(const float* __restrict__ Wq, const float* __restrict__ Wk,
                             const float* __restrict__ Wv, const float* __restrict__ Wo) {
    const float* W = (blockIdx.z == 0) ? Wq : (blockIdx.z == 1) ? Wk
                   : (blockIdx.z == 2) ? Wv : Wo;
    __shared__ float sm[32][33];
    int n0 = blockIdx.x * 32, k0 = blockIdx.y * 32;
    int tx = threadIdx.x, ty = threadIdx.y;   // 32 x 8
#pragma unroll
    for (int j = 0; j < 4; j++)
        sm[ty + j * 8][tx] = W[(size_t)(k0 + ty + j * 8) * D_MODEL + n0 + tx];
    __syncthreads();
#pragma unroll
    for (int j = 0; j < 4; j++) {
        int n = n0 + ty + j * 8, k = k0 + tx;
        float v = sm[tx][ty + j * 8] * 256.0f;
        __half h = __float2half_rn(v);
        __half l = __float2half_rn(v - __half2float(h));
        size_t o = (size_t)(blockIdx.z * 1024 + n) * KE + k;
        g_B2[o] = h;                     // hi
        g_B2[o + 1024] = l;              // lo
    }
}

// ---------------------------------------------------------------------------
// fp16 GEMM, exact 3-product split: C = AhBh + AlBh + AhBl (+ ~2^-24).
// Natural K=1024, BK=32 per stage (stage holds Ah|Al and Bh|Bl 32-col strips).
// 128x128 tile, S=3 stages, one __syncthreads per kb, 2 CTAs/SM.
// ---------------------------------------------------------------------------
#define PITCH 72                         // 64 + 8 pad (144B rows, 16B aligned)
#define TILE_B (128 * PITCH * 2)         // 18432 B per array (A or B region)
#define STAGE_B (2 * TILE_B)             // 36864 B per stage

template <bool QKV>
__global__ __launch_bounds__(256, 2) void gemm_mma(float* __restrict__ Cout) {
    extern __shared__ __align__(16) __half sm[];
    const int t = threadIdx.x;
    const int warp = t >> 5, lane = t & 31;
    const int m0 = blockIdx.y * 128, n0 = blockIdx.x * 128;
    const int wm0 = (warp >> 1) * 32;
    const int wn0 = (warp & 1) * 64;

    const __half* Bbase = g_B2 + (QKV ? 0 : (size_t)3072 * KE);
    const uint32_t sbase = smem_u32(sm);

    const int lr = t >> 3, lc = (t & 7) * 8;
    // natural-K column gather: stage col c<32 -> hi col kb*32+c ; c>=32 -> lo
    const int gcol_off = (lc < 32) ? lc : (lc + 992);   // +992 = 1024 - 32

    auto issue_stage = [&](int slot, int kb) {
        uint32_t so = sbase + (uint32_t)slot * STAGE_B;
#pragma unroll
        for (int p = 0; p < 4; p++) {
            int row = lr + p * 32;
            uint32_t sofs = ((uint32_t)row * PITCH + lc) * 2;
            size_t gc = (size_t)kb * 32 + gcol_off;
            cp16(so + sofs,          g_A2 + (size_t)(m0 + row) * KE + gc);
            cp16(so + TILE_B + sofs, Bbase + (size_t)(n0 + row) * KE + gc);
        }
        CP_COMMIT();
    };

    float d[2][8][4];
#pragma unroll
    for (int i = 0; i < 2; i++)
#pragma unroll
        for (int j = 0; j < 8; j++)
#pragma unroll
            for (int u = 0; u < 4; u++) d[i][j][u] = 0.f;

    const int arow = wm0 + (lane & 15);
    const int acolq = (lane >> 4) * 8;
    const int brow2 = wn0 + (lane >> 4) * 8 + (lane & 7);
    const int bcol2 = ((lane >> 3) & 1) * 8;

    issue_stage(0, 0);
    issue_stage(1, 1);

    for (int kb = 0; kb < 32; kb++) {
        CP_WAIT(1);
        __syncthreads();
        if (kb + 2 < 32) issue_stage((kb + 2) % 3, kb + 2);
        uint32_t so = sbase + (uint32_t)(kb % 3) * STAGE_B;
#pragma unroll
        for (int ks = 0; ks < 2; ks++) {
            uint32_t ah[2][4], al[2][4];
#pragma unroll
            for (int i = 0; i < 2; i++) {
                uint32_t rbase = so + (uint32_t)(arow + i * 16) * PITCH * 2;
                ldm_x4(ah[i], rbase + (ks * 16 + acolq) * 2);
                ldm_x4(al[i], rbase + (32 + ks * 16 + acolq) * 2);
            }
#pragma unroll
            for (int jp = 0; jp < 4; jp++) {
                uint32_t rbase = so + TILE_B + (uint32_t)(brow2 + jp * 16) * PITCH * 2;
                uint32_t bh4[4], bl4[4];
                ldm_x4(bh4, rbase + (ks * 16 + bcol2) * 2);
                ldm_x4(bl4, rbase + (32 + ks * 16 + bcol2) * 2);
#pragma unroll
                for (int i = 0; i < 2; i++) {
                    mma_hf(d[i][2 * jp],     ah[i], bh4 + 0);
                    mma_hf(d[i][2 * jp + 1], ah[i], bh4 + 2);
                    mma_hf(d[i][2 * jp],     al[i], bh4 + 0);
                    mma_hf(d[i][2 * jp + 1], al[i], bh4 + 2);
                    mma_hf(d[i][2 * jp],     ah[i], bl4 + 0);
                    mma_hf(d[i][2 * jp + 1], ah[i], bl4 + 2);
                }
            }
        }
    }

    // epilogue (results carry x256 from W scaling)
    const float inv256 = 1.0f / 256.0f;
#pragma unroll
    for (int i = 0; i < 2; i++) {
        int r = m0 + wm0 + i * 16 + (lane >> 2);
#pragma unroll
        for (int j = 0; j < 8; j++) {
            int n = n0 + wn0 + j * 8 + (lane & 3) * 2;
#pragma unroll
            for (int half_ = 0; half_ < 2; half_++) {
                int rr = r + half_ * 8;
                float v0 = d[i][j][2 * half_ + 0] * inv256;
                float v1 = d[i][j][2 * half_ + 1] * inv256;
                if (QKV) {
                    int z = n >> 10, hd = (n >> 6) & 15, dd = n & 63;
                    if (z < 2) {
                        __half* q = (z == 0 ? g_Q2 : g_K2) + (size_t)hd * HSZ + (size_t)rr * 128 + dd;
                        __half h0 = __float2half_rn(v0), h1 = __float2half_rn(v1);
                        *(__half2*)q = __halves2half2(h0, h1);
                        *(__half2*)(q + 64) = __halves2half2(
                            __float2half_rn(v0 - __half2float(h0)),
                            __float2half_rn(v1 - __half2float(h1)));
                    } else {
                        __half* vv = g_V + (size_t)hd * HSZV + (size_t)rr * 64 + dd;
                        *(__half2*)vv = __halves2half2(__float2half_rn(v0), __float2half_rn(v1));
                    }
                } else {
                    *(float2*)(Cout + (size_t)rr * D_MODEL + n) = make_float2(v0, v1);
                }
            }
        }
    }
}

// ---------------------------------------------------------------------------
// fp16 flash attention. CTA = (head, 128 q). S = QhKh + QlKh + QhKl (exact);
// P fp16, V single fp16. 64-key tiles, S=3 stages, one sync per tile.
// ---------------------------------------------------------------------------
#define PK 136                           // K'/Q' pitch (128+8) -> 272B rows
#define PV 72                            // V pitch (64+8) -> 144B rows
#define KARR_B (64 * PK * 2)             // 17408
#define VARR_B (64 * PV * 2)             // 9216
#define AST_B  (KARR_B + VARR_B)         // 26624 per stage

__global__ __launch_bounds__(256, 2) void attn_mma() {
    extern __shared__ __align__(16) char smem[];
    const uint32_t sb = smem_u32(smem);
    const int t = threadIdx.x, w = t >> 5, lane = t & 31;
    const int h = blockIdx.y, q0 = blockIdx.x * 128;

    const __half* Q2 = g_Q2 + (size_t)h * HSZ;
    const __half* K2 = g_K2 + (size_t)h * HSZ;
    const __half* Vp = g_V  + (size_t)h * HSZV;

    // ---- stage Q' (128x128) into stage region, extract fragments ----
    {
        int row = t >> 4, colc = (t & 15) * 8;
#pragma unroll
        for (int p = 0; p < 8; p++) {
            int r = row + p * 16;
            cp16(sb + ((uint32_t)r * PK + colc) * 2, Q2 + (size_t)(q0 + r) * 128 + colc);
        }
        CP_COMMIT();
        CP_WAIT(0);
        __syncthreads();
    }
    uint32_t qf[8][4];   // ks 0-3: Qh chunks, ks 4-7: Ql chunks
    {
        int arow = w * 16 + (lane & 15);
        int acol = (lane >> 4) * 8;
#pragma unroll
        for (int ks = 0; ks < 8; ks++)
            ldm_x4(qf[ks], sb + ((uint32_t)arow * PK + ks * 16 + acol) * 2);
    }
    __syncthreads();

    auto issue_kv = [&](int slot, int i) {
        int k0 = i * 64;
        uint32_t base = sb + (uint32_t)slot * AST_B;
        {
            int row = t >> 4, colc = (t & 15) * 8;
#pragma unroll
            for (int p = 0; p < 4; p++) {
                int r = row + p * 16;
                cp16(base + ((uint32_t)r * PK + colc) * 2, K2 + (size_t)(k0 + r) * 128 + colc);
            }
        }
        {
            int row = t >> 3, colc = (t & 7) * 8;
#pragma unroll
            for (int p = 0; p < 2; p++) {
                int r = row + p * 32;
                cp16(base + KARR_B + ((uint32_t)r * PV + colc) * 2, Vp + (size_t)(k0 + r) * 64 + colc);
            }
        }
        CP_COMMIT();
    };

    issue_kv(0, 0);
    issue_kv(1, 1);

    float o[8][4];
#pragma unroll
    for (int j = 0; j < 8; j++)
#pragma unroll
        for (int u = 0; u < 4; u++) o[j][u] = 0.f;
    float m_r = -1e30f, m_r8 = -1e30f, l_r = 0.f, l_r8 = 0.f;

    const int cq = (lane & 3) * 2;
    const int q_r = q0 + w * 16 + (lane >> 2);
    const float* bh = g_bias + h * 4096 + 2047 - q_r;

    const int k_r = (lane >> 4) * 8 + (lane & 7);
    const int k_c = ((lane >> 3) & 1) * 8;
    const int v_r = (lane & 7) + ((lane >> 3) & 1) * 8;
    const int v_c = (lane >> 4) * 8;

    for (int i = 0; i < 32; i++) {
        CP_WAIT(1);
        __syncthreads();
        if (i + 2 < 32) issue_kv((i + 2) % 3, i + 2);
        uint32_t stb = sb + (uint32_t)(i % 3) * AST_B;
        const int k0 = i * 64;

        // S = QhKh + QlKh + QhKl (3-product exact split over natural d=64)
        float s[8][4];
#pragma unroll
        for (int j = 0; j < 8; j++)
#pragma unroll
            for (int u = 0; u < 4; u++) s[j][u] = 0.f;
#pragma unroll
        for (int ks = 0; ks < 4; ks++) {
#pragma unroll
            for (int jp = 0; jp < 4; jp++) {
                uint32_t rbase = stb + (uint32_t)((jp * 16 + k_r) * PK) * 2;
                uint32_t kh4[4], kl4[4];
                ldm_x4(kh4, rbase + (ks * 16 + k_c) * 2);
                ldm_x4(kl4, rbase + (64 + ks * 16 + k_c) * 2);
                mma_hf(s[2 * jp],     qf[ks],     kh4 + 0);
                mma_hf(s[2 * jp + 1], qf[ks],     kh4 + 2);
                mma_hf(s[2 * jp],     qf[4 + ks], kh4 + 0);
                mma_hf(s[2 * jp + 1], qf[4 + ks], kh4 + 2);
                mma_hf(s[2 * jp],     qf[ks],     kl4 + 0);
                mma_hf(s[2 * jp + 1], qf[ks],     kl4 + 2);
            }
        }

        // bias + online softmax
        float rmax = -1e30f, rmax8 = -1e30f;
#pragma unroll
        for (int j = 0; j < 8; j++) {
            const float* bp = bh + k0 + j * 8 + cq;
            s[j][0] += __ldg(bp);
            s[j][1] += __ldg(bp + 1);
            s[j][2] += __ldg(bp - 8);
            s[j][3] += __ldg(bp - 7);
            rmax  = fmaxf(rmax,  fmaxf(s[j][0], s[j][1]));
            rmax8 = fmaxf(rmax8, fmaxf(s[j][2], s[j][3]));
        }
#pragma unroll
        for (int off = 1; off <= 2; off <<= 1) {
            rmax  = fmaxf(rmax,  __shfl_xor_sync(0xffffffffu, rmax,  off));
            rmax8 = fmaxf(rmax8, __shfl_xor_sync(0xffffffffu, rmax8, off));
        }
        float mn  = fmaxf(m_r,  rmax);
        float mn8 = fmaxf(m_r8, rmax8);
        float cr  = __expf(m_r - mn);
        float cr8 = __expf(m_r8 - mn8);
        m_r = mn; m_r8 = mn8;
        float sum = 0.f, sum8 = 0.f;
#pragma unroll
        for (int j = 0; j < 8; j++) {
            s[j][0] = __expf(s[j][0] - mn);
            s[j][1] = __expf(s[j][1] - mn);
            s[j][2] = __expf(s[j][2] - mn8);
            s[j][3] = __expf(s[j][3] - mn8);
            sum  += s[j][0] + s[j][1];
            sum8 += s[j][2] + s[j][3];
        }
#pragma unroll
        for (int off = 1; off <= 2; off <<= 1) {
            sum  += __shfl_xor_sync(0xffffffffu, sum,  off);
            sum8 += __shfl_xor_sync(0xffffffffu, sum8, off);
        }
        l_r  = l_r  * cr  + sum;
        l_r8 = l_r8 * cr8 + sum8;
#pragma unroll
        for (int j = 0; j < 8; j++) {
            o[j][0] *= cr;  o[j][1] *= cr;
            o[j][2] *= cr8; o[j][3] *= cr8;
        }

        // P (fp16) from fragments
        uint32_t pa[4][4];
#pragma unroll
        for (int ks = 0; ks < 4; ks++) {
            pa[ks][0] = pack_f16(s[2 * ks][0], s[2 * ks][1]);
            pa[ks][1] = pack_f16(s[2 * ks][2], s[2 * ks][3]);
            pa[ks][2] = pack_f16(s[2 * ks + 1][0], s[2 * ks + 1][1]);
            pa[ks][3] = pack_f16(s[2 * ks + 1][2], s[2 * ks + 1][3]);
        }

        // O += P V
#pragma unroll
        for (int ks = 0; ks < 4; ks++) {
#pragma unroll
            for (int jp = 0; jp < 4; jp++) {
                uint32_t v4[4];
                ldm_x4t(v4, stb + KARR_B +
                            ((uint32_t)((ks * 16 + v_r) * PV + jp * 16 + v_c)) * 2);
                mma_hf(o[2 * jp],     pa[ks], v4 + 0);
                mma_hf(o[2 * jp + 1], pa[ks], v4 + 2);
            }
        }
    }

    // epilogue: ctx -> A' rows (hi | lo) for the out GEMM
    float ir = 1.f / l_r, ir8 = 1.f / l_r8;
#pragma unroll
    for (int j = 0; j < 8; j++) {
        int col = h * 64 + j * 8 + cq;
#pragma unroll
        for (int half_ = 0; half_ < 2; half_++) {
            int rr = q_r + half_ * 8;
            float sc = half_ ? ir8 : ir;
            float v0 = o[j][2 * half_ + 0] * sc;
            float v1 = o[j][2 * half_ + 1] * sc;
            __half h0 = __float2half_rn(v0), h1 = __float2half_rn(v1);
            __half* dst = g_A2 + (size_t)rr * KE + col;
            *(__half2*)dst = __halves2half2(h0, h1);
            *(__half2*)(dst + 1024) = __halves2half2(
                __float2half_rn(v0 - __half2float(h0)),
                __float2half_rn(v1 - __half2float(h1)));
        }
    }
}

// ---------------------------------------------------------------------------
extern "C" void kernel_launch(void* const* d_in, const int* in_sizes, int n_in,
                              void* d_out, int out_size) {
    const float* X   = (const float*)d_in[0];
    const float* Wq  = (const float*)d_in[1];
    const float* Wk  = (const float*)d_in[2];
    const float* Wv  = (const float*)d_in[3];
    const float* Wo  = (const float*)d_in[4];
    const float* rel = (const float*)d_in[5];
    float* out = (float*)d_out;

    const int gemm_smem = 3 * STAGE_B;      // 110592
    const int attn_smem = 3 * AST_B;        // 79872 (>= 34816 Q staging)
    cudaFuncSetAttribute(gemm_mma<true>,  cudaFuncAttributeMaxDynamicSharedMemorySize, gemm_smem);
    cudaFuncSetAttribute(gemm_mma<false>, cudaFuncAttributeMaxDynamicSharedMemorySize, gemm_smem);
    cudaFuncSetAttribute(attn_mma,        cudaFuncAttributeMaxDynamicSharedMemorySize, attn_smem);

    bias_kernel<<<(N_HEADS * 4095 + 255) / 256, 256>>>(rel);
    convA_kernel<<<(S_LEN * D_MODEL / 4) / 256, 256>>>(X);
    convB_kernel<<<dim3(32, 32, 4), dim3(32, 8)>>>(Wq, Wk, Wv, Wo);
    gemm_mma<true><<<dim3(24, 16), 256, gemm_smem>>>(nullptr);
    attn_mma<<<dim3(16, 16), 256, attn_smem>>>();
    gemm_mma<false><<<dim3(8, 16), 256, gemm_smem>>>(out);
}

// round 10
// speedup vs baseline: 1.0316x; 1.0316x over previous
#include <cuda_runtime.h>
#include <cuda_fp16.h>
#include <math.h>
#include <cstdint>

#define S_LEN 2048
#define D_MODEL 1024
#define N_HEADS 16
#define D_KV 64
#define KE 2048              // A'/B' width: [hi(1024) | lo(1024)]
#define HSZ (S_LEN * 128)    // per-head Q'/K' plane (d'=128: [hi|lo])
#define HSZV (S_LEN * 64)    // per-head V plane

// ---------------- scratch (__device__ globals; no allocs) -------------------
__device__ float g_bias[N_HEADS * 4096];                 // [h][delta+2047]
__device__ __align__(16) __half g_A2[S_LEN * KE];        // A' rows: [Ah | Al]
__device__ __align__(16) __half g_B2[4096 * KE];         // B' rows: [Bh | Bl], W x256
__device__ __align__(16) __half g_Q2[N_HEADS * HSZ];     // [h][s][ Qh(64) | Ql(64) ]
__device__ __align__(16) __half g_K2[N_HEADS * HSZ];     // [h][s][ Kh(64) | Kl(64) ]
__device__ __align__(16) __half g_V [N_HEADS * HSZV];    // [h][s][64] single fp16

__device__ __forceinline__ uint32_t smem_u32(const void* p) {
    uint32_t a;
    asm("{ .reg .u64 t; cvta.to.shared.u64 t, %1; cvt.u32.u64 %0, t; }" : "=r"(a) : "l"(p));
    return a;
}

// ---------------- mma / ldmatrix / cp.async primitives ----------------------
__device__ __forceinline__ void ldm_x4(uint32_t* r, uint32_t addr) {
    asm volatile("ldmatrix.sync.aligned.m8n8.x4.shared.b16 {%0,%1,%2,%3}, [%4];"
                 : "=r"(r[0]), "=r"(r[1]), "=r"(r[2]), "=r"(r[3]) : "r"(addr));
}
__device__ __forceinline__ void ldm_x4t(uint32_t* r, uint32_t addr) {
    asm volatile("ldmatrix.sync.aligned.m8n8.x4.trans.shared.b16 {%0,%1,%2,%3}, [%4];"
                 : "=r"(r[0]), "=r"(r[1]), "=r"(r[2]), "=r"(r[3]) : "r"(addr));
}
__device__ __forceinline__ void mma_hf(float* d, const uint32_t* a, const uint32_t* b) {
    asm volatile("mma.sync.aligned.m16n8k16.row.col.f32.f16.f16.f32 "
                 "{%0,%1,%2,%3}, {%4,%5,%6,%7}, {%8,%9}, {%0,%1,%2,%3};"
                 : "+f"(d[0]), "+f"(d[1]), "+f"(d[2]), "+f"(d[3])
                 : "r"(a[0]), "r"(a[1]), "r"(a[2]), "r"(a[3]), "r"(b[0]), "r"(b[1]));
}
__device__ __forceinline__ void cp16(uint32_t saddr, const void* gaddr) {
    asm volatile("cp.async.cg.shared.global [%0], [%1], 16;" :: "r"(saddr), "l"(gaddr));
}
#define CP_COMMIT() asm volatile("cp.async.commit_group;" ::: "memory")
#define CP_WAIT(n)  asm volatile("cp.async.wait_group %0;" :: "n"(n) : "memory")

__device__ __forceinline__ uint32_t pack_f16(float lo, float hi) {
    uint32_t r;
    asm("cvt.rn.f16x2.f32 %0, %1, %2;" : "=r"(r) : "f"(hi), "f"(lo));
    return r;
}

// ---------------------------------------------------------------------------
// Bias LUT
// ---------------------------------------------------------------------------
__global__ void bias_kernel(const float* __restrict__ rel_bias) {
    int idx = blockIdx.x * blockDim.x + threadIdx.x;
    if (idx >= N_HEADS * 4095) return;
    int h = idx / 4095;
    int di = idx % 4095;
    int delta = di - 2047;
    int bucket = (delta > 0) ? 16 : 0;
    int rp = abs(delta);
    if (rp < 8) {
        bucket += rp;
    } else {
        float lr = logf((float)rp * 0.125f) / 2.7725887f;
        int large = 8 + (int)(lr * 8.0f);
        bucket += (large < 15) ? large : 15;
    }
    g_bias[h * 4096 + di] = rel_bias[bucket * N_HEADS + h];
}

// ---------------------------------------------------------------------------
// Converters: fp32 -> fp16 hi/lo split
// ---------------------------------------------------------------------------
__global__ void convA_kernel(const float* __restrict__ X) {
    int i = (blockIdx.x * blockDim.x + threadIdx.x) * 4;   // over 2048x1024
    int row = i >> 10, col = i & 1023;
    float4 v = *(const float4*)(X + i);
    float x[4] = {v.x, v.y, v.z, v.w};
    __half hi[4], lo[4];
#pragma unroll
    for (int u = 0; u < 4; u++) {
        hi[u] = __float2half_rn(x[u]);
        lo[u] = __float2half_rn(x[u] - __half2float(hi[u]));
    }
    __half* dst = g_A2 + (size_t)row * KE + col;
    *(__half2*)(dst + 0) = __halves2half2(hi[0], hi[1]);
    *(__half2*)(dst + 2) = __halves2half2(hi[2], hi[3]);
    *(__half2*)(dst + 1024) = __halves2half2(lo[0], lo[1]);
    *(__half2*)(dst + 1026) = __halves2half2(lo[2], lo[3]);
}

// Transpose + split W*256 into g_B2 rows [Bh|Bl]; z: 0=Wq 1=Wk 2=Wv 3=Wo
__global__ void convB_kernel(const float* __restrict__ Wq, const float* __restrict__ Wk,
                             const float* __restrict__ Wv, const float* __restrict__ Wo) {
    const float* W = (blockIdx.z == 0) ? Wq : (blockIdx.z == 1) ? Wk
                   : (blockIdx.z == 2) ? Wv : Wo;
    __shared__ float sm[32][33];
    int n0 = blockIdx.x * 32, k0 = blockIdx.y * 32;
    int tx = threadIdx.x, ty = threadIdx.y;   // 32 x 8
#pragma unroll
    for (int j = 0; j < 4; j++)
        sm[ty + j * 8][tx] = W[(size_t)(k0 + ty + j * 8) * D_MODEL + n0 + tx];
    __syncthreads();
#pragma unroll
    for (int j = 0; j < 4; j++) {
        int n = n0 + ty + j * 8, k = k0 + tx;
        float v = sm[tx][ty + j * 8] * 256.0f;
        __half h = __float2half_rn(v);
        __half l = __float2half_rn(v - __half2float(h));
        size_t o = (size_t)(blockIdx.z * 1024 + n) * KE + k;
        g_B2[o] = h;                     // hi
        g_B2[o + 1024] = l;              // lo
    }
}

// ---------------------------------------------------------------------------
// fp16 GEMM, hi/lo split. full=3-product (exact), !full=2-product (drops AhBl).
// 128x128 tile, BK=32 natural, S=3, one sync per kb, 2 CTAs/SM.
// ---------------------------------------------------------------------------
#define PITCH 72                         // 64 + 8 pad (144B rows, 16B aligned)
#define TILE_B (128 * PITCH * 2)         // 18432 B per array (A or B region)
#define STAGE_B (2 * TILE_B)             // 36864 B per stage

template <bool QKV>
__global__ __launch_bounds__(256, 2) void gemm_mma(float* __restrict__ Cout) {
    extern __shared__ __align__(16) __half sm[];
    const int t = threadIdx.x;
    const int warp = t >> 5, lane = t & 31;
    const int m0 = blockIdx.y * 128, n0 = blockIdx.x * 128;
    const int wm0 = (warp >> 1) * 32;
    const int wn0 = (warp & 1) * 64;
    // Q,K columns need the exact 3-product; V / out columns use 2-product.
    const bool full = QKV && (blockIdx.x < 16);

    const __half* Bbase = g_B2 + (QKV ? 0 : (size_t)3072 * KE);
    const uint32_t sbase = smem_u32(sm);

    const int lr = t >> 3, lc = (t & 7) * 8;
    const int gcol_off = (lc < 32) ? lc : (lc + 992);   // hi strip | lo strip

    auto issue_stage = [&](int slot, int kb) {
        uint32_t so = sbase + (uint32_t)slot * STAGE_B;
#pragma unroll
        for (int p = 0; p < 4; p++) {
            int row = lr + p * 32;
            uint32_t sofs = ((uint32_t)row * PITCH + lc) * 2;
            size_t gc = (size_t)kb * 32 + gcol_off;
            cp16(so + sofs,          g_A2 + (size_t)(m0 + row) * KE + gc);
            cp16(so + TILE_B + sofs, Bbase + (size_t)(n0 + row) * KE + gc);
        }
        CP_COMMIT();
    };

    float d[2][8][4];
#pragma unroll
    for (int i = 0; i < 2; i++)
#pragma unroll
        for (int j = 0; j < 8; j++)
#pragma unroll
            for (int u = 0; u < 4; u++) d[i][j][u] = 0.f;

    const int arow = wm0 + (lane & 15);
    const int acolq = (lane >> 4) * 8;
    const int brow2 = wn0 + (lane >> 4) * 8 + (lane & 7);
    const int bcol2 = ((lane >> 3) & 1) * 8;

    issue_stage(0, 0);
    issue_stage(1, 1);

    for (int kb = 0; kb < 32; kb++) {
        CP_WAIT(1);
        __syncthreads();
        if (kb + 2 < 32) issue_stage((kb + 2) % 3, kb + 2);
        uint32_t so = sbase + (uint32_t)(kb % 3) * STAGE_B;
#pragma unroll
        for (int ks = 0; ks < 2; ks++) {
            uint32_t ah[2][4], al[2][4];
#pragma unroll
            for (int i = 0; i < 2; i++) {
                uint32_t rbase = so + (uint32_t)(arow + i * 16) * PITCH * 2;
                ldm_x4(ah[i], rbase + (ks * 16 + acolq) * 2);
                ldm_x4(al[i], rbase + (32 + ks * 16 + acolq) * 2);
            }
#pragma unroll
            for (int jp = 0; jp < 4; jp++) {
                uint32_t rbase = so + TILE_B + (uint32_t)(brow2 + jp * 16) * PITCH * 2;
                uint32_t bh4[4];
                ldm_x4(bh4, rbase + (ks * 16 + bcol2) * 2);
                // product-major order: accumulator chains spaced by 4
                mma_hf(d[0][2 * jp],     ah[0], bh4 + 0);
                mma_hf(d[1][2 * jp],     ah[1], bh4 + 0);
                mma_hf(d[0][2 * jp + 1], ah[0], bh4 + 2);
                mma_hf(d[1][2 * jp + 1], ah[1], bh4 + 2);
                mma_hf(d[0][2 * jp],     al[0], bh4 + 0);
                mma_hf(d[1][2 * jp],     al[1], bh4 + 0);
                mma_hf(d[0][2 * jp + 1], al[0], bh4 + 2);
                mma_hf(d[1][2 * jp + 1], al[1], bh4 + 2);
                if (full) {
                    uint32_t bl4[4];
                    ldm_x4(bl4, rbase + (32 + ks * 16 + bcol2) * 2);
                    mma_hf(d[0][2 * jp],     ah[0], bl4 + 0);
                    mma_hf(d[1][2 * jp],     ah[1], bl4 + 0);
                    mma_hf(d[0][2 * jp + 1], ah[0], bl4 + 2);
                    mma_hf(d[1][2 * jp + 1], ah[1], bl4 + 2);
                }
            }
        }
    }

    // epilogue (results carry x256 from W scaling)
    const float inv256 = 1.0f / 256.0f;
#pragma unroll
    for (int i = 0; i < 2; i++) {
        int r = m0 + wm0 + i * 16 + (lane >> 2);
#pragma unroll
        for (int j = 0; j < 8; j++) {
            int n = n0 + wn0 + j * 8 + (lane & 3) * 2;
#pragma unroll
            for (int half_ = 0; half_ < 2; half_++) {
                int rr = r + half_ * 8;
                float v0 = d[i][j][2 * half_ + 0] * inv256;
                float v1 = d[i][j][2 * half_ + 1] * inv256;
                if (QKV) {
                    int z = n >> 10, hd = (n >> 6) & 15, dd = n & 63;
                    if (z < 2) {
                        __half* q = (z == 0 ? g_Q2 : g_K2) + (size_t)hd * HSZ + (size_t)rr * 128 + dd;
                        __half h0 = __float2half_rn(v0), h1 = __float2half_rn(v1);
                        *(__half2*)q = __halves2half2(h0, h1);
                        *(__half2*)(q + 64) = __halves2half2(
                            __float2half_rn(v0 - __half2float(h0)),
                            __float2half_rn(v1 - __half2float(h1)));
                    } else {
                        __half* vv = g_V + (size_t)hd * HSZV + (size_t)rr * 64 + dd;
                        *(__half2*)vv = __halves2half2(__float2half_rn(v0), __float2half_rn(v1));
                    }
                } else {
                    *(float2*)(Cout + (size_t)rr * D_MODEL + n) = make_float2(v0, v1);
                }
            }
        }
    }
}

// ---------------------------------------------------------------------------
// fp16 flash attention, software-pipelined across tiles:
//   per iteration: softmax(i) -> barrier/issue -> QK(i+1) interleaved with PV(i)
// QK exact 3-product (QhKh+QlKh+QhKl); P fp16; V fp16. S=4 stages.
// ---------------------------------------------------------------------------
#define PK 136                           // K'/Q' pitch (128+8) -> 272B rows
#define PV 72                            // V pitch (64+8) -> 144B rows
#define KARR_B (64 * PK * 2)             // 17408
#define VARR_B (64 * PV * 2)             // 9216
#define AST_B  (KARR_B + VARR_B)         // 26624 per stage
#define AST_N  4

__global__ __launch_bounds__(256, 2) void attn_mma() {
    extern __shared__ __align__(16) char smem[];
    const uint32_t sb = smem_u32(smem);
    const int t = threadIdx.x, w = t >> 5, lane = t & 31;
    const int h = blockIdx.y, q0 = blockIdx.x * 128;

    const __half* Q2 = g_Q2 + (size_t)h * HSZ;
    const __half* K2 = g_K2 + (size_t)h * HSZ;
    const __half* Vp = g_V  + (size_t)h * HSZV;

    // ---- stage Q' (128x128), extract fragments ----
    {
        int row = t >> 4, colc = (t & 15) * 8;
#pragma unroll
        for (int p = 0; p < 8; p++) {
            int r = row + p * 16;
            cp16(sb + ((uint32_t)r * PK + colc) * 2, Q2 + (size_t)(q0 + r) * 128 + colc);
        }
        CP_COMMIT();
        CP_WAIT(0);
        __syncthreads();
    }
    uint32_t qf[8][4];   // ks 0-3: Qh, ks 4-7: Ql
    {
        int arow = w * 16 + (lane & 15);
        int acol = (lane >> 4) * 8;
#pragma unroll
        for (int ks = 0; ks < 8; ks++)
            ldm_x4(qf[ks], sb + ((uint32_t)arow * PK + ks * 16 + acol) * 2);
    }
    __syncthreads();

    auto issue_kv = [&](int slot, int i) {
        int k0 = i * 64;
        uint32_t base = sb + (uint32_t)slot * AST_B;
        {
            int row = t >> 4, colc = (t & 15) * 8;
#pragma unroll
            for (int p = 0; p < 4; p++) {
                int r = row + p * 16;
                cp16(base + ((uint32_t)r * PK + colc) * 2, K2 + (size_t)(k0 + r) * 128 + colc);
            }
        }
        {
            int row = t >> 3, colc = (t & 7) * 8;
#pragma unroll
            for (int p = 0; p < 2; p++) {
                int r = row + p * 32;
                cp16(base + KARR_B + ((uint32_t)r * PV + colc) * 2, Vp + (size_t)(k0 + r) * 64 + colc);
            }
        }
        CP_COMMIT();
    };

    issue_kv(0, 0);
    issue_kv(1, 1);
    issue_kv(2, 2);

    const int cq = (lane & 3) * 2;
    const int q_r = q0 + w * 16 + (lane >> 2);
    const float* bh = g_bias + h * 4096 + 2047 - q_r;

    const int k_r = (lane >> 4) * 8 + (lane & 7);
    const int k_c = ((lane >> 3) & 1) * 8;
    const int v_r = (lane & 7) + ((lane >> 3) & 1) * 8;
    const int v_c = (lane >> 4) * 8;

    float o[8][4];
#pragma unroll
    for (int j = 0; j < 8; j++)
#pragma unroll
        for (int u = 0; u < 4; u++) o[j][u] = 0.f;
    float m_r = -1e30f, m_r8 = -1e30f, l_r = 0.f, l_r8 = 0.f;
    float s[8][4];

    // QK of tile `i` from stage base `stb_k` into s (3-product exact)
    auto qk_tile = [&](uint32_t stb_k) {
#pragma unroll
        for (int j = 0; j < 8; j++)
#pragma unroll
            for (int u = 0; u < 4; u++) s[j][u] = 0.f;
#pragma unroll
        for (int ks = 0; ks < 4; ks++) {
#pragma unroll
            for (int jp = 0; jp < 4; jp++) {
                uint32_t rbase = stb_k + (uint32_t)((jp * 16 + k_r) * PK) * 2;
                uint32_t kh4[4], kl4[4];
                ldm_x4(kh4, rbase + (ks * 16 + k_c) * 2);
                ldm_x4(kl4, rbase + (64 + ks * 16 + k_c) * 2);
                mma_hf(s[2 * jp],     qf[ks],     kh4 + 0);
                mma_hf(s[2 * jp + 1], qf[ks],     kh4 + 2);
                mma_hf(s[2 * jp],     qf[4 + ks], kh4 + 0);
                mma_hf(s[2 * jp + 1], qf[4 + ks], kh4 + 2);
                mma_hf(s[2 * jp],     qf[ks],     kl4 + 0);
                mma_hf(s[2 * jp + 1], qf[ks],     kl4 + 2);
            }
        }
    };

    // prologue: S(0)
    CP_WAIT(2);
    __syncthreads();
    qk_tile(sb + 0 * AST_B);

    for (int i = 0; i < 32; i++) {
        const int k0 = i * 64;

        // ---- softmax(i) ----
        float rmax = -1e30f, rmax8 = -1e30f;
#pragma unroll
        for (int j = 0; j < 8; j++) {
            const float* bp = bh + k0 + j * 8 + cq;
            s[j][0] += __ldg(bp);
            s[j][1] += __ldg(bp + 1);
            s[j][2] += __ldg(bp - 8);
            s[j][3] += __ldg(bp - 7);
            rmax  = fmaxf(rmax,  fmaxf(s[j][0], s[j][1]));
            rmax8 = fmaxf(rmax8, fmaxf(s[j][2], s[j][3]));
        }
#pragma unroll
        for (int off = 1; off <= 2; off <<= 1) {
            rmax  = fmaxf(rmax,  __shfl_xor_sync(0xffffffffu, rmax,  off));
            rmax8 = fmaxf(rmax8, __shfl_xor_sync(0xffffffffu, rmax8, off));
        }
        float mn  = fmaxf(m_r,  rmax);
        float mn8 = fmaxf(m_r8, rmax8);
        float cr  = __expf(m_r - mn);
        float cr8 = __expf(m_r8 - mn8);
        m_r = mn; m_r8 = mn8;
        float sum = 0.f, sum8 = 0.f;
#pragma unroll
        for (int j = 0; j < 8; j++) {
            s[j][0] = __expf(s[j][0] - mn);
            s[j][1] = __expf(s[j][1] - mn);
            s[j][2] = __expf(s[j][2] - mn8);
            s[j][3] = __expf(s[j][3] - mn8);
            sum  += s[j][0] + s[j][1];
            sum8 += s[j][2] + s[j][3];
        }
#pragma unroll
        for (int off = 1; off <= 2; off <<= 1) {
            sum  += __shfl_xor_sync(0xffffffffu, sum,  off);
            sum8 += __shfl_xor_sync(0xffffffffu, sum8, off);
        }
        l_r  = l_r  * cr  + sum;
        l_r8 = l_r8 * cr8 + sum8;
#pragma unroll
        for (int j = 0; j < 8; j++) {
            o[j][0] *= cr;  o[j][1] *= cr;
            o[j][2] *= cr8; o[j][3] *= cr8;
        }
        uint32_t pa[4][4];
#pragma unroll
        for (int ks = 0; ks < 4; ks++) {
            pa[ks][0] = pack_f16(s[2 * ks][0], s[2 * ks][1]);
            pa[ks][1] = pack_f16(s[2 * ks][2], s[2 * ks][3]);
            pa[ks][2] = pack_f16(s[2 * ks + 1][0], s[2 * ks + 1][1]);
            pa[ks][3] = pack_f16(s[2 * ks + 1][2], s[2 * ks + 1][3]);
        }

        // ---- barrier + staging for next tile ----
        const bool not_last = (i + 1 < 32);
        if (not_last) {
            if (i < 30) { CP_WAIT(1); } else { CP_WAIT(0); }
            __syncthreads();
            if (i + 3 < 32) issue_kv((i + 3) & 3, i + 3);
        }

        // ---- compute: QK(i+1) (independent) interleaved with PV(i) ----
        uint32_t stb_v = sb + (uint32_t)(i & 3) * AST_B;
        if (not_last)
            qk_tile(sb + (uint32_t)((i + 1) & 3) * AST_B);
#pragma unroll
        for (int ks = 0; ks < 4; ks++) {
#pragma unroll
            for (int jp = 0; jp < 4; jp++) {
                uint32_t v4[4];
                ldm_x4t(v4, stb_v + KARR_B +
                            ((uint32_t)((ks * 16 + v_r) * PV + jp * 16 + v_c)) * 2);
                mma_hf(o[2 * jp],     pa[ks], v4 + 0);
                mma_hf(o[2 * jp + 1], pa[ks], v4 + 2);
            }
        }
    }

    // epilogue: ctx -> A' rows (hi | lo) for the out GEMM
    float ir = 1.f / l_r, ir8 = 1.f / l_r8;
#pragma unroll
    for (int j = 0; j < 8; j++) {
        int col = h * 64 + j * 8 + cq;
#pragma unroll
        for (int half_ = 0; half_ < 2; half_++) {
            int rr = q_r + half_ * 8;
            float sc = half_ ? ir8 : ir;
            float v0 = o[j][2 * half_ + 0] * sc;
            float v1 = o[j][2 * half_ + 1] * sc;
            __half h0 = __float2half_rn(v0), h1 = __float2half_rn(v1);
            __half* dst = g_A2 + (size_t)rr * KE + col;
            *(__half2*)dst = __halves2half2(h0, h1);
            *(__half2*)(dst + 1024) = __halves2half2(
                __float2half_rn(v0 - __half2float(h0)),
                __float2half_rn(v1 - __half2float(h1)));
        }
    }
}

// ---------------------------------------------------------------------------
extern "C" void kernel_launch(void* const* d_in, const int* in_sizes, int n_in,
                              void* d_out, int out_size) {
    const float* X   = (const float*)d_in[0];
    const float* Wq  = (const float*)d_in[1];
    const float* Wk  = (const float*)d_in[2];
    const float* Wv  = (const float*)d_in[3];
    const float* Wo  = (const float*)d_in[4];
    const float* rel = (const float*)d_in[5];
    float* out = (float*)d_out;

    const int gemm_smem = 3 * STAGE_B;      // 110592
    const int attn_smem = AST_N * AST_B;    // 106496 (>= 34816 Q staging)
    cudaFuncSetAttribute(gemm_mma<true>,  cudaFuncAttributeMaxDynamicSharedMemorySize, gemm_smem);
    cudaFuncSetAttribute(gemm_mma<false>, cudaFuncAttributeMaxDynamicSharedMemorySize, gemm_smem);
    cudaFuncSetAttribute(attn_mma,        cudaFuncAttributeMaxDynamicSharedMemorySize, attn_smem);

    bias_kernel<<<(N_HEADS * 4095 + 255) / 256, 256>>>(rel);
    convA_kernel<<<(S_LEN * D_MODEL / 4) / 256, 256>>>(X);
    convB_kernel<<<dim3(32, 32, 4), dim3(32, 8)>>>(Wq, Wk, Wv, Wo);
    gemm_mma<true><<<dim3(24, 16), 256, gemm_smem>>>(nullptr);
    attn_mma<<<dim3(16, 16), 256, attn_smem>>>();
    gemm_mma<false><<<dim3(8, 16), 256, gemm_smem>>>(out);
}

// round 11
// speedup vs baseline: 1.0324x; 1.0008x over previous
#include <cuda_runtime.h>
#include <cuda_fp16.h>
#include <math.h>
#include <cstdint>

#define S_LEN 2048
#define D_MODEL 1024
#define N_HEADS 16
#define D_KV 64
#define KE 2048              // A'/B' width: [hi(1024) | lo(1024)]
#define HSZ (S_LEN * 128)    // per-head Q'/K' plane (d'=128: [hi|lo])
#define HSZV (S_LEN * 64)    // per-head V plane

// ---------------- scratch (__device__ globals; no allocs) -------------------
__device__ float g_bias[N_HEADS * 4096];                 // [h][delta+2047]
__device__ __align__(16) __half g_A2[S_LEN * KE];        // A' rows: [Ah | Al]
__device__ __align__(16) __half g_B2[4096 * KE];         // B' rows: [Bh | Bl], W x256
__device__ __align__(16) __half g_Q2[N_HEADS * HSZ];     // [h][s][ Qh(64) | Ql(64) ]
__device__ __align__(16) __half g_K2[N_HEADS * HSZ];     // [h][s][ Kh(64) | Kl(64) ]
__device__ __align__(16) __half g_V [N_HEADS * HSZV];    // [h][s][64] single fp16

__device__ __forceinline__ uint32_t smem_u32(const void* p) {
    uint32_t a;
    asm("{ .reg .u64 t; cvta.to.shared.u64 t, %1; cvt.u32.u64 %0, t; }" : "=r"(a) : "l"(p));
    return a;
}

// ---------------- mma / ldmatrix / cp.async primitives ----------------------
__device__ __forceinline__ void ldm_x4(uint32_t* r, uint32_t addr) {
    asm volatile("ldmatrix.sync.aligned.m8n8.x4.shared.b16 {%0,%1,%2,%3}, [%4];"
                 : "=r"(r[0]), "=r"(r[1]), "=r"(r[2]), "=r"(r[3]) : "r"(addr));
}
__device__ __forceinline__ void ldm_x4t(uint32_t* r, uint32_t addr) {
    asm volatile("ldmatrix.sync.aligned.m8n8.x4.trans.shared.b16 {%0,%1,%2,%3}, [%4];"
                 : "=r"(r[0]), "=r"(r[1]), "=r"(r[2]), "=r"(r[3]) : "r"(addr));
}
__device__ __forceinline__ void mma_hf(float* d, const uint32_t* a, const uint32_t* b) {
    asm volatile("mma.sync.aligned.m16n8k16.row.col.f32.f16.f16.f32 "
                 "{%0,%1,%2,%3}, {%4,%5,%6,%7}, {%8,%9}, {%0,%1,%2,%3};"
                 : "+f"(d[0]), "+f"(d[1]), "+f"(d[2]), "+f"(d[3])
                 : "r"(a[0]), "r"(a[1]), "r"(a[2]), "r"(a[3]), "r"(b[0]), "r"(b[1]));
}
__device__ __forceinline__ void cp16(uint32_t saddr, const void* gaddr) {
    asm volatile("cp.async.cg.shared.global [%0], [%1], 16;" :: "r"(saddr), "l"(gaddr));
}
#define CP_COMMIT() asm volatile("cp.async.commit_group;" ::: "memory")
#define CP_WAIT(n)  asm volatile("cp.async.wait_group %0;" :: "n"(n) : "memory")

__device__ __forceinline__ uint32_t pack_f16(float lo, float hi) {
    uint32_t r;
    asm("cvt.rn.f16x2.f32 %0, %1, %2;" : "=r"(r) : "f"(hi), "f"(lo));
    return r;
}

// ---------------------------------------------------------------------------
// Bias LUT
// ---------------------------------------------------------------------------
__global__ void bias_kernel(const float* __restrict__ rel_bias) {
    int idx = blockIdx.x * blockDim.x + threadIdx.x;
    if (idx >= N_HEADS * 4095) return;
    int h = idx / 4095;
    int di = idx % 4095;
    int delta = di - 2047;
    int bucket = (delta > 0) ? 16 : 0;
    int rp = abs(delta);
    if (rp < 8) {
        bucket += rp;
    } else {
        float lr = logf((float)rp * 0.125f) / 2.7725887f;
        int large = 8 + (int)(lr * 8.0f);
        bucket += (large < 15) ? large : 15;
    }
    g_bias[h * 4096 + di] = rel_bias[bucket * N_HEADS + h];
}

// ---------------------------------------------------------------------------
// Converters: fp32 -> fp16 hi/lo split
// ---------------------------------------------------------------------------
__global__ void convA_kernel(const float* __restrict__ X) {
    int i = (blockIdx.x * blockDim.x + threadIdx.x) * 4;   // over 2048x1024
    int row = i >> 10, col = i & 1023;
    float4 v = *(const float4*)(X + i);
    float x[4] = {v.x, v.y, v.z, v.w};
    __half hi[4], lo[4];
#pragma unroll
    for (int u = 0; u < 4; u++) {
        hi[u] = __float2half_rn(x[u]);
        lo[u] = __float2half_rn(x[u] - __half2float(hi[u]));
    }
    __half* dst = g_A2 + (size_t)row * KE + col;
    *(__half2*)(dst + 0) = __halves2half2(hi[0], hi[1]);
    *(__half2*)(dst + 2) = __halves2half2(hi[2], hi[3]);
    *(__half2*)(dst + 1024) = __halves2half2(lo[0], lo[1]);
    *(__half2*)(dst + 1026) = __halves2half2(lo[2], lo[3]);
}

// Transpose + split W*256 into g_B2 rows [Bh|Bl]; z: 0=Wq 1=Wk 2=Wv 3=Wo
__global__ void convB_kernel(const float* __restrict__ Wq, const float* __restrict__ Wk,
                             const float* __restrict__ Wv, const float* __restrict__ Wo) {
    const float* W = (blockIdx.z == 0) ? Wq : (blockIdx.z == 1) ? Wk
                   : (blockIdx.z == 2) ? Wv : Wo;
    __shared__ float sm[32][33];
    int n0 = blockIdx.x * 32, k0 = blockIdx.y * 32;
    int tx = threadIdx.x, ty = threadIdx.y;   // 32 x 8
#pragma unroll
    for (int j = 0; j < 4; j++)
        sm[ty + j * 8][tx] = W[(size_t)(k0 + ty + j * 8) * D_MODEL + n0 + tx];
    __syncthreads();
#pragma unroll
    for (int j = 0; j < 4; j++) {
        int n = n0 + ty + j * 8, k = k0 + tx;
        float v = sm[tx][ty + j * 8] * 256.0f;
        __half h = __float2half_rn(v);
        __half l = __float2half_rn(v - __half2float(h));
        size_t o = (size_t)(blockIdx.z * 1024 + n) * KE + k;
        g_B2[o] = h;                     // hi
        g_B2[o + 1024] = l;              // lo
    }
}

// ---------------------------------------------------------------------------
// fp16 GEMM, hi/lo split. full=3-product (exact), !full=2-product (drops AhBl).
// 128x128 tile, BK=32 natural, S=3, one sync per kb, 2 CTAs/SM.
// ---------------------------------------------------------------------------
#define PITCH 72                         // 64 + 8 pad (144B rows, 16B aligned)
#define TILE_B (128 * PITCH * 2)         // 18432 B per array (A or B region)
#define STAGE_B (2 * TILE_B)             // 36864 B per stage

template <bool QKV>
__global__ __launch_bounds__(256, 2) void gemm_mma(float* __restrict__ Cout) {
    extern __shared__ __align__(16) __half sm[];
    const int t = threadIdx.x;
    const int warp = t >> 5, lane = t & 31;
    const int m0 = blockIdx.y * 128, n0 = blockIdx.x * 128;
    const int wm0 = (warp >> 1) * 32;
    const int wn0 = (warp & 1) * 64;
    // Q,K columns need the exact 3-product; V / out columns use 2-product.
    const bool full = QKV && (blockIdx.x < 16);

    const __half* Bbase = g_B2 + (QKV ? 0 : (size_t)3072 * KE);
    const uint32_t sbase = smem_u32(sm);

    const int lr = t >> 3, lc = (t & 7) * 8;
    const int gcol_off = (lc < 32) ? lc : (lc + 992);   // hi strip | lo strip

    auto issue_stage = [&](int slot, int kb) {
        uint32_t so = sbase + (uint32_t)slot * STAGE_B;
#pragma unroll
        for (int p = 0; p < 4; p++) {
            int row = lr + p * 32;
            uint32_t sofs = ((uint32_t)row * PITCH + lc) * 2;
            size_t gc = (size_t)kb * 32 + gcol_off;
            cp16(so + sofs,          g_A2 + (size_t)(m0 + row) * KE + gc);
            cp16(so + TILE_B + sofs, Bbase + (size_t)(n0 + row) * KE + gc);
        }
        CP_COMMIT();
    };

    float d[2][8][4];
#pragma unroll
    for (int i = 0; i < 2; i++)
#pragma unroll
        for (int j = 0; j < 8; j++)
#pragma unroll
            for (int u = 0; u < 4; u++) d[i][j][u] = 0.f;

    const int arow = wm0 + (lane & 15);
    const int acolq = (lane >> 4) * 8;
    const int brow2 = wn0 + (lane >> 4) * 8 + (lane & 7);
    const int bcol2 = ((lane >> 3) & 1) * 8;

    issue_stage(0, 0);
    issue_stage(1, 1);

    for (int kb = 0; kb < 32; kb++) {
        CP_WAIT(1);
        __syncthreads();
        if (kb + 2 < 32) issue_stage((kb + 2) % 3, kb + 2);
        uint32_t so = sbase + (uint32_t)(kb % 3) * STAGE_B;
#pragma unroll
        for (int ks = 0; ks < 2; ks++) {
            uint32_t ah[2][4], al[2][4];
#pragma unroll
            for (int i = 0; i < 2; i++) {
                uint32_t rbase = so + (uint32_t)(arow + i * 16) * PITCH * 2;
                ldm_x4(ah[i], rbase + (ks * 16 + acolq) * 2);
                ldm_x4(al[i], rbase + (32 + ks * 16 + acolq) * 2);
            }
#pragma unroll
            for (int jp = 0; jp < 4; jp++) {
                uint32_t rbase = so + TILE_B + (uint32_t)(brow2 + jp * 16) * PITCH * 2;
                uint32_t bh4[4];
                ldm_x4(bh4, rbase + (ks * 16 + bcol2) * 2);
                // product-major order: accumulator chains spaced by 4
                mma_hf(d[0][2 * jp],     ah[0], bh4 + 0);
                mma_hf(d[1][2 * jp],     ah[1], bh4 + 0);
                mma_hf(d[0][2 * jp + 1], ah[0], bh4 + 2);
                mma_hf(d[1][2 * jp + 1], ah[1], bh4 + 2);
                mma_hf(d[0][2 * jp],     al[0], bh4 + 0);
                mma_hf(d[1][2 * jp],     al[1], bh4 + 0);
                mma_hf(d[0][2 * jp + 1], al[0], bh4 + 2);
                mma_hf(d[1][2 * jp + 1], al[1], bh4 + 2);
                if (full) {
                    uint32_t bl4[4];
                    ldm_x4(bl4, rbase + (32 + ks * 16 + bcol2) * 2);
                    mma_hf(d[0][2 * jp],     ah[0], bl4 + 0);
                    mma_hf(d[1][2 * jp],     ah[1], bl4 + 0);
                    mma_hf(d[0][2 * jp + 1], ah[0], bl4 + 2);
                    mma_hf(d[1][2 * jp + 1], ah[1], bl4 + 2);
                }
            }
        }
    }

    // epilogue (results carry x256 from W scaling)
    const float inv256 = 1.0f / 256.0f;
#pragma unroll
    for (int i = 0; i < 2; i++) {
        int r = m0 + wm0 + i * 16 + (lane >> 2);
#pragma unroll
        for (int j = 0; j < 8; j++) {
            int n = n0 + wn0 + j * 8 + (lane & 3) * 2;
#pragma unroll
            for (int half_ = 0; half_ < 2; half_++) {
                int rr = r + half_ * 8;
                float v0 = d[i][j][2 * half_ + 0] * inv256;
                float v1 = d[i][j][2 * half_ + 1] * inv256;
                if (QKV) {
                    int z = n >> 10, hd = (n >> 6) & 15, dd = n & 63;
                    if (z < 2) {
                        __half* q = (z == 0 ? g_Q2 : g_K2) + (size_t)hd * HSZ + (size_t)rr * 128 + dd;
                        __half h0 = __float2half_rn(v0), h1 = __float2half_rn(v1);
                        *(__half2*)q = __halves2half2(h0, h1);
                        *(__half2*)(q + 64) = __halves2half2(
                            __float2half_rn(v0 - __half2float(h0)),
                            __float2half_rn(v1 - __half2float(h1)));
                    } else {
                        __half* vv = g_V + (size_t)hd * HSZV + (size_t)rr * 64 + dd;
                        *(__half2*)vv = __halves2half2(__float2half_rn(v0), __float2half_rn(v1));
                    }
                } else {
                    *(float2*)(Cout + (size_t)rr * D_MODEL + n) = make_float2(v0, v1);
                }
            }
        }
    }
}

// ---------------------------------------------------------------------------
// fp16 flash attention, software-pipelined across tiles:
//   per iteration: softmax(i) -> barrier/issue -> QK(i+1) interleaved with PV(i)
// QK exact 3-product (QhKh+QlKh+QhKl); P fp16; V fp16. S=4 stages.
// ---------------------------------------------------------------------------
#define PK 136                           // K'/Q' pitch (128+8) -> 272B rows
#define PV 72                            // V pitch (64+8) -> 144B rows
#define KARR_B (64 * PK * 2)             // 17408
#define VARR_B (64 * PV * 2)             // 9216
#define AST_B  (KARR_B + VARR_B)         // 26624 per stage
#define AST_N  4

__global__ __launch_bounds__(256, 2) void attn_mma() {
    extern __shared__ __align__(16) char smem[];
    const uint32_t sb = smem_u32(smem);
    const int t = threadIdx.x, w = t >> 5, lane = t & 31;
    const int h = blockIdx.y, q0 = blockIdx.x * 128;

    const __half* Q2 = g_Q2 + (size_t)h * HSZ;
    const __half* K2 = g_K2 + (size_t)h * HSZ;
    const __half* Vp = g_V  + (size_t)h * HSZV;

    // ---- stage Q' (128x128), extract fragments ----
    {
        int row = t >> 4, colc = (t & 15) * 8;
#pragma unroll
        for (int p = 0; p < 8; p++) {
            int r = row + p * 16;
            cp16(sb + ((uint32_t)r * PK + colc) * 2, Q2 + (size_t)(q0 + r) * 128 + colc);
        }
        CP_COMMIT();
        CP_WAIT(0);
        __syncthreads();
    }
    uint32_t qf[8][4];   // ks 0-3: Qh, ks 4-7: Ql
    {
        int arow = w * 16 + (lane & 15);
        int acol = (lane >> 4) * 8;
#pragma unroll
        for (int ks = 0; ks < 8; ks++)
            ldm_x4(qf[ks], sb + ((uint32_t)arow * PK + ks * 16 + acol) * 2);
    }
    __syncthreads();

    auto issue_kv = [&](int slot, int i) {
        int k0 = i * 64;
        uint32_t base = sb + (uint32_t)slot * AST_B;
        {
            int row = t >> 4, colc = (t & 15) * 8;
#pragma unroll
            for (int p = 0; p < 4; p++) {
                int r = row + p * 16;
                cp16(base + ((uint32_t)r * PK + colc) * 2, K2 + (size_t)(k0 + r) * 128 + colc);
            }
        }
        {
            int row = t >> 3, colc = (t & 7) * 8;
#pragma unroll
            for (int p = 0; p < 2; p++) {
                int r = row + p * 32;
                cp16(base + KARR_B + ((uint32_t)r * PV + colc) * 2, Vp + (size_t)(k0 + r) * 64 + colc);
            }
        }
        CP_COMMIT();
    };

    issue_kv(0, 0);
    issue_kv(1, 1);
    issue_kv(2, 2);

    const int cq = (lane & 3) * 2;
    const int q_r = q0 + w * 16 + (lane >> 2);
    const float* bh = g_bias + h * 4096 + 2047 - q_r;

    const int k_r = (lane >> 4) * 8 + (lane & 7);
    const int k_c = ((lane >> 3) & 1) * 8;
    const int v_r = (lane & 7) + ((lane >> 3) & 1) * 8;
    const int v_c = (lane >> 4) * 8;

    float o[8][4];
#pragma unroll
    for (int j = 0; j < 8; j++)
#pragma unroll
        for (int u = 0; u < 4; u++) o[j][u] = 0.f;
    float m_r = -1e30f, m_r8 = -1e30f, l_r = 0.f, l_r8 = 0.f;
    float s[8][4];

    // QK of tile `i` from stage base `stb_k` into s (3-product exact)
    auto qk_tile = [&](uint32_t stb_k) {
#pragma unroll
        for (int j = 0; j < 8; j++)
#pragma unroll
            for (int u = 0; u < 4; u++) s[j][u] = 0.f;
#pragma unroll
        for (int ks = 0; ks < 4; ks++) {
#pragma unroll
            for (int jp = 0; jp < 4; jp++) {
                uint32_t rbase = stb_k + (uint32_t)((jp * 16 + k_r) * PK) * 2;
                uint32_t kh4[4], kl4[4];
                ldm_x4(kh4, rbase + (ks * 16 + k_c) * 2);
                ldm_x4(kl4, rbase + (64 + ks * 16 + k_c) * 2);
                mma_hf(s[2 * jp],     qf[ks],     kh4 + 0);
                mma_hf(s[2 * jp + 1], qf[ks],     kh4 + 2);
                mma_hf(s[2 * jp],     qf[4 + ks], kh4 + 0);
                mma_hf(s[2 * jp + 1], qf[4 + ks], kh4 + 2);
                mma_hf(s[2 * jp],     qf[ks],     kl4 + 0);
                mma_hf(s[2 * jp + 1], qf[ks],     kl4 + 2);
            }
        }
    };

    // prologue: S(0)
    CP_WAIT(2);
    __syncthreads();
    qk_tile(sb + 0 * AST_B);

    for (int i = 0; i < 32; i++) {
        const int k0 = i * 64;

        // ---- softmax(i) ----
        float rmax = -1e30f, rmax8 = -1e30f;
#pragma unroll
        for (int j = 0; j < 8; j++) {
            const float* bp = bh + k0 + j * 8 + cq;
            s[j][0] += __ldg(bp);
            s[j][1] += __ldg(bp + 1);
            s[j][2] += __ldg(bp - 8);
            s[j][3] += __ldg(bp - 7);
            rmax  = fmaxf(rmax,  fmaxf(s[j][0], s[j][1]));
            rmax8 = fmaxf(rmax8, fmaxf(s[j][2], s[j][3]));
        }
#pragma unroll
        for (int off = 1; off <= 2; off <<= 1) {
            rmax  = fmaxf(rmax,  __shfl_xor_sync(0xffffffffu, rmax,  off));
            rmax8 = fmaxf(rmax8, __shfl_xor_sync(0xffffffffu, rmax8, off));
        }
        float mn  = fmaxf(m_r,  rmax);
        float mn8 = fmaxf(m_r8, rmax8);
        float cr  = __expf(m_r - mn);
        float cr8 = __expf(m_r8 - mn8);
        m_r = mn; m_r8 = mn8;
        float sum = 0.f, sum8 = 0.f;
#pragma unroll
        for (int j = 0; j < 8; j++) {
            s[j][0] = __expf(s[j][0] - mn);
            s[j][1] = __expf(s[j][1] - mn);
            s[j][2] = __expf(s[j][2] - mn8);
            s[j][3] = __expf(s[j][3] - mn8);
            sum  += s[j][0] + s[j][1];
            sum8 += s[j][2] + s[j][3];
        }
#pragma unroll
        for (int off = 1; off <= 2; off <<= 1) {
            sum  += __shfl_xor_sync(0xffffffffu, sum,  off);
            sum8 += __shfl_xor_sync(0xffffffffu, sum8, off);
        }
        l_r  = l_r  * cr  + sum;
        l_r8 = l_r8 * cr8 + sum8;
#pragma unroll
        for (int j = 0; j < 8; j++) {
            o[j][0] *= cr;  o[j][1] *= cr;
            o[j][2] *= cr8; o[j][3] *= cr8;
        }
        uint32_t pa[4][4];
#pragma unroll
        for (int ks = 0; ks < 4; ks++) {
            pa[ks][0] = pack_f16(s[2 * ks][0], s[2 * ks][1]);
            pa[ks][1] = pack_f16(s[2 * ks][2], s[2 * ks][3]);
            pa[ks][2] = pack_f16(s[2 * ks + 1][0], s[2 * ks + 1][1]);
            pa[ks][3] = pack_f16(s[2 * ks + 1][2], s[2 * ks + 1][3]);
        }

        // ---- barrier + staging for next tile ----
        const bool not_last = (i + 1 < 32);
        if (not_last) {
            if (i < 30) { CP_WAIT(1); } else { CP_WAIT(0); }
            __syncthreads();
            if (i + 3 < 32) issue_kv((i + 3) & 3, i + 3);
        }

        // ---- compute: QK(i+1) (independent) interleaved with PV(i) ----
        uint32_t stb_v = sb + (uint32_t)(i & 3) * AST_B;
        if (not_last)
            qk_tile(sb + (uint32_t)((i + 1) & 3) * AST_B);
#pragma unroll
        for (int ks = 0; ks < 4; ks++) {
#pragma unroll
            for (int jp = 0; jp < 4; jp++) {
                uint32_t v4[4];
                ldm_x4t(v4, stb_v + KARR_B +
                            ((uint32_t)((ks * 16 + v_r) * PV + jp * 16 + v_c)) * 2);
                mma_hf(o[2 * jp],     pa[ks], v4 + 0);
                mma_hf(o[2 * jp + 1], pa[ks], v4 + 2);
            }
        }
    }

    // epilogue: ctx -> A' rows (hi | lo) for the out GEMM
    float ir = 1.f / l_r, ir8 = 1.f / l_r8;
#pragma unroll
    for (int j = 0; j < 8; j++) {
        int col = h * 64 + j * 8 + cq;
#pragma unroll
        for (int half_ = 0; half_ < 2; half_++) {
            int rr = q_r + half_ * 8;
            float sc = half_ ? ir8 : ir;
            float v0 = o[j][2 * half_ + 0] * sc;
            float v1 = o[j][2 * half_ + 1] * sc;
            __half h0 = __float2half_rn(v0), h1 = __float2half_rn(v1);
            __half* dst = g_A2 + (size_t)rr * KE + col;
            *(__half2*)dst = __halves2half2(h0, h1);
            *(__half2*)(dst + 1024) = __halves2half2(
                __float2half_rn(v0 - __half2float(h0)),
                __float2half_rn(v1 - __half2float(h1)));
        }
    }
}

// ---------------------------------------------------------------------------
extern "C" void kernel_launch(void* const* d_in, const int* in_sizes, int n_in,
                              void* d_out, int out_size) {
    const float* X   = (const float*)d_in[0];
    const float* Wq  = (const float*)d_in[1];
    const float* Wk  = (const float*)d_in[2];
    const float* Wv  = (const float*)d_in[3];
    const float* Wo  = (const float*)d_in[4];
    const float* rel = (const float*)d_in[5];
    float* out = (float*)d_out;

    const int gemm_smem = 3 * STAGE_B;      // 110592
    const int attn_smem = AST_N * AST_B;    // 106496 (>= 34816 Q staging)
    cudaFuncSetAttribute(gemm_mma<true>,  cudaFuncAttributeMaxDynamicSharedMemorySize, gemm_smem);
    cudaFuncSetAttribute(gemm_mma<false>, cudaFuncAttributeMaxDynamicSharedMemorySize, gemm_smem);
    cudaFuncSetAttribute(attn_mma,        cudaFuncAttributeMaxDynamicSharedMemorySize, attn_smem);

    bias_kernel<<<(N_HEADS * 4095 + 255) / 256, 256>>>(rel);
    convA_kernel<<<(S_LEN * D_MODEL / 4) / 256, 256>>>(X);
    convB_kernel<<<dim3(32, 32, 4), dim3(32, 8)>>>(Wq, Wk, Wv, Wo);
    gemm_mma<true><<<dim3(24, 16), 256, gemm_smem>>>(nullptr);
    attn_mma<<<dim3(16, 16), 256, attn_smem>>>();
    gemm_mma<false><<<dim3(8, 16), 256, gemm_smem>>>(out);
}